// round 12
// baseline (speedup 1.0000x reference)
#include <cuda_runtime.h>
#include <cuda_fp16.h>
#include <cuda_bf16.h>
#include <cstdint>

#define NN 100000
#define EE 3200000
#define DH 128
#define EPS 1e-5f

// ---------------- device scratch (static, no allocation) ----------------
__device__ int    g_cnt[NN];
__device__ int    g_cursor[NN];
__device__ int    g_rowoff[NN];
__device__ float  g_dinv[NN];
__device__ int    g_col[EE];
__device__ int    g_blocksum[128];
__device__ int    g_blockpref[128];
__device__ float  g_bnsum1[DH];
__device__ float  g_bnsq1[DH];
__device__ float  g_bnsum2[DH];
__device__ float  g_bnsq2[DH];
__device__ __half g_msg[NN * DH];      // GEMM out * dinv (fp16)
__device__ float  g_buf[NN * DH];      // agg out (fp32)

__device__ __forceinline__ uint32_t smem_u32(const void* p) {
    uint32_t a;
    asm("{ .reg .u64 tmp; cvta.to.shared.u64 tmp, %1; cvt.u32.u64 %0, tmp; }"
        : "=r"(a) : "l"(p));
    return a;
}

#define LDSM_X4(r0, r1, r2, r3, addr) \
    asm volatile("ldmatrix.sync.aligned.m8n8.x4.shared.b16 {%0,%1,%2,%3}, [%4];" \
                 : "=r"(r0), "=r"(r1), "=r"(r2), "=r"(r3) : "r"(addr))

#define MMA_BF16(d, a, b0, b1) \
    asm volatile("mma.sync.aligned.m16n8k16.row.col.f32.bf16.bf16.f32 " \
                 "{%0,%1,%2,%3},{%4,%5,%6,%7},{%8,%9},{%0,%1,%2,%3};" \
                 : "+f"((d)[0]), "+f"((d)[1]), "+f"((d)[2]), "+f"((d)[3]) \
                 : "r"((a)[0]), "r"((a)[1]), "r"((a)[2]), "r"((a)[3]), \
                   "r"(b0), "r"(b1))

__device__ __forceinline__ uint32_t bsplit_hi2(float x, float y, float& rx, float& ry) {
    __nv_bfloat162 h;
    h.x = __float2bfloat16(x);
    h.y = __float2bfloat16(y);
    rx = x - __bfloat162float(h.x);
    ry = y - __bfloat162float(h.y);
    return *reinterpret_cast<uint32_t*>(&h);
}
__device__ __forceinline__ uint32_t pack_bf2(float x, float y) {
    __nv_bfloat162 h;
    h.x = __float2bfloat16(x);
    h.y = __float2bfloat16(y);
    return *reinterpret_cast<uint32_t*>(&h);
}

// ---------------- graph build ----------------
__global__ void k_zero_graph(int n) {
    int i = blockIdx.x * blockDim.x + threadIdx.x;
    if (i < n) { g_cnt[i] = 0; g_cursor[i] = 0; }
    if (blockIdx.x == 0 && threadIdx.x < DH) {
        g_bnsum1[threadIdx.x] = 0.f; g_bnsq1[threadIdx.x] = 0.f;
        g_bnsum2[threadIdx.x] = 0.f; g_bnsq2[threadIdx.x] = 0.f;
    }
}

__global__ void k_hist(const int* __restrict__ ei, int e) {
    int i = blockIdx.x * blockDim.x + threadIdx.x;
    if (i < e) atomicAdd(&g_cnt[ei[e + i]], 1);
}

__global__ void k_dinv(int n) {
    int i = blockIdx.x * blockDim.x + threadIdx.x;
    if (i < n) g_dinv[i] = rsqrtf((float)(g_cnt[i] + 1));
}

__global__ void k_scan1(int n) {
    __shared__ int warpsum[32];
    int i = blockIdx.x * 1024 + threadIdx.x;
    int v = (i < n) ? g_cnt[i] : 0;
    int lane = threadIdx.x & 31, wid = threadIdx.x >> 5;
    int incl = v;
#pragma unroll
    for (int o = 1; o < 32; o <<= 1) {
        int t = __shfl_up_sync(0xffffffffu, incl, o);
        if (lane >= o) incl += t;
    }
    if (lane == 31) warpsum[wid] = incl;
    __syncthreads();
    if (wid == 0) {
        int s = warpsum[lane];
        int si = s;
#pragma unroll
        for (int o = 1; o < 32; o <<= 1) {
            int t = __shfl_up_sync(0xffffffffu, si, o);
            if (lane >= o) si += t;
        }
        warpsum[lane] = si - s;
    }
    __syncthreads();
    int excl = incl - v + warpsum[wid];
    if (i < n) g_rowoff[i] = excl;
    if (threadIdx.x == 1023) g_blocksum[blockIdx.x] = excl + v;
}

__global__ void k_scan2(int nb) {
    __shared__ int s[128];
    int t = threadIdx.x;
    int v = (t < nb) ? g_blocksum[t] : 0;
    s[t] = v;
    __syncthreads();
    for (int o = 1; o < 128; o <<= 1) {
        int x = (t >= o) ? s[t - o] : 0;
        __syncthreads();
        s[t] += x;
        __syncthreads();
    }
    if (t < nb) g_blockpref[t] = s[t] - v;
}

__global__ void k_scan3(int n) {
    int i = blockIdx.x * blockDim.x + threadIdx.x;
    if (i < n) g_rowoff[i] += g_blockpref[i >> 10];
}

__global__ void k_fill(const int* __restrict__ ei, int e) {
    int i = blockIdx.x * blockDim.x + threadIdx.x;
    if (i < e) {
        int s = ei[i];
        int d = ei[e + i];
        int pos = atomicAdd(&g_cursor[d], 1);
        g_col[g_rowoff[d] + pos] = s;
    }
}

// ======== HMMA GEMM (R9-proven): C(fp16) = dinv[row]*(relu(bn(A))@W) ========
// bf16 hi/lo split, 3 mma.sync passes, fp32 accum.
// FUSE: BN params computed in-kernel from sums (k_bnparams fused away).
#define LDS_H 40

template <int NCOLS, bool FUSE>
__global__ __launch_bounds__(256) void k_mma(const float* __restrict__ A,
                                             const float* __restrict__ W,
                                             __half* __restrict__ C,
                                             const float* __restrict__ sumArr,
                                             const float* __restrict__ sqArr,
                                             const float* __restrict__ gma,
                                             const float* __restrict__ bta,
                                             float inv_n, int n) {
    constexpr int NT = NCOLS / 16;
    constexpr int NSH = (NCOLS == 128) ? 7 : 6;
    __shared__ __align__(16) __nv_bfloat16 sAhi[128 * LDS_H];
    __shared__ __align__(16) __nv_bfloat16 sAlo[128 * LDS_H];
    __shared__ __align__(16) __nv_bfloat16 sWhi[NCOLS * LDS_H];
    __shared__ __align__(16) __nv_bfloat16 sWlo[NCOLS * LDS_H];
    __shared__ float s_scale[DH];
    __shared__ float s_shift[DH];

    int tid = threadIdx.x;
    int wid = tid >> 5, lane = tid & 31;
    int warp_m = wid & 3, warp_n = wid >> 2;
    int row0 = blockIdx.x * 128;
    int g = lane >> 2, t = lane & 3;

    if (FUSE && tid < DH) {
        float mean = sumArr[tid] * inv_n;
        float var = sqArr[tid] * inv_n - mean * mean;
        float s = gma[tid] * rsqrtf(var + EPS);
        s_scale[tid] = s;
        s_shift[tid] = bta[tid] - mean * s;
    }
    if (FUSE) __syncthreads();

    uint32_t uAhi = smem_u32(sAhi), uAlo = smem_u32(sAlo);
    uint32_t uWhi = smem_u32(sWhi), uWlo = smem_u32(sWlo);

    float acc[2][NT][4];
#pragma unroll
    for (int i = 0; i < 2; i++)
#pragma unroll
        for (int j = 0; j < NT; j++)
#pragma unroll
            for (int q = 0; q < 4; q++) acc[i][j][q] = 0.f;

    uint32_t a_off = ((warp_m * 32 + (lane & 15)) * LDS_H + (lane >> 4) * 8) * 2;
    uint32_t b_off = ((warp_n * (NCOLS / 2) + (lane & 7) + ((lane & 16) ? 8 : 0)) * LDS_H
                      + ((lane >> 3) & 1) * 8) * 2;

    for (int kc = 0; kc < 4; kc++) {
#pragma unroll
        for (int it = 0; it < 4; it++) {
            int idx = tid + it * 256;
            int r = idx >> 3;
            int c4 = idx & 7;
            int row = row0 + r;
            float4 v = make_float4(0.f, 0.f, 0.f, 0.f);
            if (row < n)
                v = reinterpret_cast<const float4*>(A)[(size_t)row * 32 + kc * 8 + c4];
            if (FUSE) {
                int k = kc * 32 + c4 * 4;
                v.x = fmaxf(0.f, v.x * s_scale[k + 0] + s_shift[k + 0]);
                v.y = fmaxf(0.f, v.y * s_scale[k + 1] + s_shift[k + 1]);
                v.z = fmaxf(0.f, v.z * s_scale[k + 2] + s_shift[k + 2]);
                v.w = fmaxf(0.f, v.w * s_scale[k + 3] + s_shift[k + 3]);
            }
            float rx, ry, rz, rw;
            uint2 hh, ll;
            hh.x = bsplit_hi2(v.x, v.y, rx, ry);
            hh.y = bsplit_hi2(v.z, v.w, rz, rw);
            ll.x = pack_bf2(rx, ry);
            ll.y = pack_bf2(rz, rw);
            int ho = r * LDS_H + c4 * 4;
            *reinterpret_cast<uint2*>(&sAhi[ho]) = hh;
            *reinterpret_cast<uint2*>(&sAlo[ho]) = ll;
        }
#pragma unroll
        for (int it = 0; it < (32 * NCOLS) / 256; it++) {
            int idx = tid + it * 256;
            int nn_ = idx & (NCOLS - 1);
            int kk_ = idx >> NSH;
            float w = W[(size_t)(kc * 32 + kk_) * NCOLS + nn_];
            __nv_bfloat16 wh = __float2bfloat16(w);
            __nv_bfloat16 wl = __float2bfloat16(w - __bfloat162float(wh));
            sWhi[nn_ * LDS_H + kk_] = wh;
            sWlo[nn_ * LDS_H + kk_] = wl;
        }
        __syncthreads();

#pragma unroll
        for (int ks = 0; ks < 2; ks++) {
            uint32_t k0b = ks * 16 * 2;
            uint32_t ah[2][4], al[2][4];
#pragma unroll
            for (int mt = 0; mt < 2; mt++) {
                uint32_t ao = a_off + k0b + mt * 16 * LDS_H * 2;
                LDSM_X4(ah[mt][0], ah[mt][1], ah[mt][2], ah[mt][3], uAhi + ao);
                LDSM_X4(al[mt][0], al[mt][1], al[mt][2], al[mt][3], uAlo + ao);
            }
#pragma unroll
            for (int nt2 = 0; nt2 < NT / 2; nt2++) {
                uint32_t bo = b_off + k0b + nt2 * 16 * LDS_H * 2;
                uint32_t bh[4], bl[4];
                LDSM_X4(bh[0], bh[1], bh[2], bh[3], uWhi + bo);
                LDSM_X4(bl[0], bl[1], bl[2], bl[3], uWlo + bo);
#pragma unroll
                for (int mt = 0; mt < 2; mt++) {
#pragma unroll
                    for (int sb = 0; sb < 2; sb++) {
                        float* d = acc[mt][nt2 * 2 + sb];
                        MMA_BF16(d, ah[mt], bh[2 * sb], bh[2 * sb + 1]);
                        MMA_BF16(d, ah[mt], bl[2 * sb], bl[2 * sb + 1]);
                        MMA_BF16(d, al[mt], bh[2 * sb], bh[2 * sb + 1]);
                    }
                }
            }
        }
        __syncthreads();
    }

    // ---- epilogue: pre-scale by dinv[row], fp16 out ----
#pragma unroll
    for (int mt = 0; mt < 2; mt++) {
        int r0 = row0 + warp_m * 32 + mt * 16 + g;
        float d0 = (r0 < n) ? g_dinv[r0] : 0.f;
        float d1 = (r0 + 8 < n) ? g_dinv[r0 + 8] : 0.f;
#pragma unroll
        for (int nt = 0; nt < NT; nt++) {
            int col = warp_n * (NCOLS / 2) + nt * 8 + 2 * t;
            if (r0 < n)
                *reinterpret_cast<__half2*>(&C[(size_t)r0 * NCOLS + col]) =
                    __floats2half2_rn(acc[mt][nt][0] * d0, acc[mt][nt][1] * d0);
            if (r0 + 8 < n)
                *reinterpret_cast<__half2*>(&C[(size_t)(r0 + 8) * NCOLS + col]) =
                    __floats2half2_rn(acc[mt][nt][2] * d1, acc[mt][nt][3] * d1);
        }
    }
}

// ---------------- aggregation over pre-scaled fp16 messages ----------------
template <int LANES, bool STATS, bool SOFTMAX>
__global__ __launch_bounds__(256) void k_agg(const uint2* __restrict__ t,
                                             float* __restrict__ outp,
                                             const float* __restrict__ bias,
                                             float* __restrict__ sumArr,
                                             float* __restrict__ sqArr, int n) {
    constexpr int SUBS = 256 / LANES;
    int sub = threadIdx.x / LANES;
    int lane = threadIdx.x % LANES;
    unsigned mask = (LANES == 32) ? 0xffffffffu : (0xffffu << (threadIdx.x & 16));
    int stride = gridDim.x * SUBS;

    float4 lsum = make_float4(0, 0, 0, 0);
    float4 lsq = make_float4(0, 0, 0, 0);
    float4 b4 = reinterpret_cast<const float4*>(bias)[lane];

    for (int node = blockIdx.x * SUBS + sub; node < n; node += stride) {
        float dn = g_dinv[node];
        uint2 u0 = t[(size_t)node * LANES + lane];
        float2 s01 = __half22float2(*reinterpret_cast<__half2*>(&u0.x));
        float2 s23 = __half22float2(*reinterpret_cast<__half2*>(&u0.y));
        float4 acc = make_float4(s01.x, s01.y, s23.x, s23.y);   // self message
        float4 acc2 = make_float4(0.f, 0.f, 0.f, 0.f);
        int start = g_rowoff[node];
        int cnt = g_cnt[node];
        int base = 0;
        for (; base + LANES <= cnt; base += LANES) {
            int s = g_col[start + base + lane];
#pragma unroll 16
            for (int k = 0; k < LANES; k++) {
                int ss = __shfl_sync(mask, s, k, LANES);
                uint2 u = t[(size_t)ss * LANES + lane];
                float2 f01 = __half22float2(*reinterpret_cast<__half2*>(&u.x));
                float2 f23 = __half22float2(*reinterpret_cast<__half2*>(&u.y));
                if (k & 1) {
                    acc2.x += f01.x; acc2.y += f01.y; acc2.z += f23.x; acc2.w += f23.y;
                } else {
                    acc.x += f01.x; acc.y += f01.y; acc.z += f23.x; acc.w += f23.y;
                }
            }
        }
        int rem = cnt - base;
        if (rem > 0) {
            int s = (lane < rem) ? g_col[start + base + lane] : 0;
            for (int k = 0; k < rem; k++) {
                int ss = __shfl_sync(mask, s, k, LANES);
                uint2 u = t[(size_t)ss * LANES + lane];
                float2 f01 = __half22float2(*reinterpret_cast<__half2*>(&u.x));
                float2 f23 = __half22float2(*reinterpret_cast<__half2*>(&u.y));
                if (k & 1) {
                    acc2.x += f01.x; acc2.y += f01.y; acc2.z += f23.x; acc2.w += f23.y;
                } else {
                    acc.x += f01.x; acc.y += f01.y; acc.z += f23.x; acc.w += f23.y;
                }
            }
        }
        acc.x += acc2.x; acc.y += acc2.y; acc.z += acc2.z; acc.w += acc2.w;
        acc.x = acc.x * dn + b4.x;
        acc.y = acc.y * dn + b4.y;
        acc.z = acc.z * dn + b4.z;
        acc.w = acc.w * dn + b4.w;

        if (SOFTMAX) {
            float m = fmaxf(fmaxf(acc.x, acc.y), fmaxf(acc.z, acc.w));
#pragma unroll
            for (int o = LANES / 2; o >= 1; o >>= 1)
                m = fmaxf(m, __shfl_xor_sync(mask, m, o, LANES));
            float4 e;
            e.x = __expf(acc.x - m); e.y = __expf(acc.y - m);
            e.z = __expf(acc.z - m); e.w = __expf(acc.w - m);
            float ssum = e.x + e.y + e.z + e.w;
#pragma unroll
            for (int o = LANES / 2; o >= 1; o >>= 1)
                ssum += __shfl_xor_sync(mask, ssum, o, LANES);
            float inv = 1.f / ssum;
            e.x *= inv; e.y *= inv; e.z *= inv; e.w *= inv;
            reinterpret_cast<float4*>(outp)[(size_t)node * LANES + lane] = e;
        } else {
            reinterpret_cast<float4*>(outp)[(size_t)node * LANES + lane] = acc;
            if (STATS) {
                lsum.x += acc.x; lsum.y += acc.y; lsum.z += acc.z; lsum.w += acc.w;
                lsq.x += acc.x * acc.x; lsq.y += acc.y * acc.y;
                lsq.z += acc.z * acc.z; lsq.w += acc.w * acc.w;
            }
        }
    }

    if constexpr (STATS) {
        __shared__ float4 ssumS[SUBS][32];
        __shared__ float4 ssqS[SUBS][32];
        ssumS[sub][lane] = lsum;
        ssqS[sub][lane] = lsq;
        __syncthreads();
        if (threadIdx.x < 32) {
            float4 a = make_float4(0, 0, 0, 0), b = make_float4(0, 0, 0, 0);
#pragma unroll
            for (int w2 = 0; w2 < SUBS; w2++) {
                float4 u = ssumS[w2][threadIdx.x], q = ssqS[w2][threadIdx.x];
                a.x += u.x; a.y += u.y; a.z += u.z; a.w += u.w;
                b.x += q.x; b.y += q.y; b.z += q.z; b.w += q.w;
            }
            int c = threadIdx.x * 4;
            atomicAdd(&sumArr[c + 0], a.x); atomicAdd(&sumArr[c + 1], a.y);
            atomicAdd(&sumArr[c + 2], a.z); atomicAdd(&sumArr[c + 3], a.w);
            atomicAdd(&sqArr[c + 0], b.x);  atomicAdd(&sqArr[c + 1], b.y);
            atomicAdd(&sqArr[c + 2], b.z);  atomicAdd(&sqArr[c + 3], b.w);
        }
    }
}

// ---------------- host ----------------
extern "C" void kernel_launch(void* const* d_in, const int* in_sizes, int n_in,
                              void* d_out, int out_size) {
    const float* x  = (const float*)d_in[0];
    const int*   ei = (const int*)d_in[1];
    const float* W1 = (const float*)d_in[2];
    const float* b1 = (const float*)d_in[3];
    const float* W2 = (const float*)d_in[4];
    const float* b2 = (const float*)d_in[5];
    const float* W3 = (const float*)d_in[6];
    const float* b3 = (const float*)d_in[7];
    const float* g1 = (const float*)d_in[8];
    const float* be1 = (const float*)d_in[9];
    const float* g2 = (const float*)d_in[10];
    const float* be2 = (const float*)d_in[11];

    int n = in_sizes[0] / 128;
    int e = in_sizes[1] / 2;

    static __half* msg = nullptr;
    static float* buf = nullptr;
    static float *sum1, *sq1, *sum2, *sq2;
    static cudaStream_t s2 = nullptr;
    static cudaEvent_t ev1 = nullptr, ev2 = nullptr;
    if (!msg) {
        cudaGetSymbolAddress((void**)&msg, g_msg);
        cudaGetSymbolAddress((void**)&buf, g_buf);
        cudaGetSymbolAddress((void**)&sum1, g_bnsum1);
        cudaGetSymbolAddress((void**)&sq1, g_bnsq1);
        cudaGetSymbolAddress((void**)&sum2, g_bnsum2);
        cudaGetSymbolAddress((void**)&sq2, g_bnsq2);
        cudaStreamCreateWithFlags(&s2, cudaStreamNonBlocking);
        cudaEventCreateWithFlags(&ev1, cudaEventDisableTiming);
        cudaEventCreateWithFlags(&ev2, cudaEventDisableTiming);
    }
    const uint2* msg2 = (const uint2*)msg;

    int nb_scan = (n + 1023) / 1024;
    int gb = (n + 127) / 128;
    int eb = (e + 255) / 256;
    int nb256 = (n + 255) / 256;
    float inv_n = 1.0f / (float)n;

    // ---- graph build on main stream; mma1 overlapped on s2 (dinv-only dep) ----
    k_zero_graph<<<nb256, 256>>>(n);
    k_hist<<<eb, 256>>>(ei, e);
    k_dinv<<<nb256, 256>>>(n);
    cudaEventRecord(ev1, 0);
    cudaStreamWaitEvent(s2, ev1, 0);
    k_mma<128, false><<<gb, 256, 0, s2>>>(x, W1, msg, nullptr, nullptr, nullptr,
                                          nullptr, inv_n, n);
    cudaEventRecord(ev2, s2);
    k_scan1<<<nb_scan, 1024>>>(n);
    k_scan2<<<1, 128>>>(nb_scan);
    k_scan3<<<nb256, 256>>>(n);
    k_fill<<<eb, 256>>>(ei, e);
    cudaStreamWaitEvent(0, ev2, 0);

    // layer 1  (BN params for layer-2 GEMM computed inside k_mma<.,true>)
    k_agg<32, true, false><<<2048, 256>>>(msg2, buf, b1, sum1, sq1, n);

    // layer 2
    k_mma<128, true><<<gb, 256>>>(buf, W2, msg, sum1, sq1, g1, be1, inv_n, n);
    k_agg<32, true, false><<<2048, 256>>>(msg2, buf, b2, sum2, sq2, n);

    // layer 3 + softmax
    k_mma<64, true><<<gb, 256>>>(buf, W3, msg, sum2, sq2, g2, be2, inv_n, n);
    k_agg<16, false, true><<<2048, 256>>>(msg2, (float*)d_out, b3, nullptr, nullptr, n);
}

// round 13
// speedup vs baseline: 1.0318x; 1.0318x over previous
#include <cuda_runtime.h>
#include <cuda_fp16.h>
#include <cuda_bf16.h>
#include <cstdint>

#define NN 100000
#define EE 3200000
#define DH 128
#define EPS 1e-5f

// ---------------- device scratch (static, no allocation) ----------------
__device__ int    g_cnt[NN];
__device__ int    g_cursor[NN];
__device__ int    g_rowoff[NN];
__device__ float  g_dinv[NN];
__device__ int    g_col[EE];
__device__ int    g_blocksum[128];
__device__ int    g_blockpref[128];
__device__ float  g_bnsum1[DH];
__device__ float  g_bnsq1[DH];
__device__ float  g_bnsum2[DH];
__device__ float  g_bnsq2[DH];
__device__ __half g_msg[NN * DH];      // GEMM out * dinv (fp16)
__device__ float  g_buf[NN * DH];      // agg out (fp32)

__device__ __forceinline__ uint32_t smem_u32(const void* p) {
    uint32_t a;
    asm("{ .reg .u64 tmp; cvta.to.shared.u64 tmp, %1; cvt.u32.u64 %0, tmp; }"
        : "=r"(a) : "l"(p));
    return a;
}

#define LDSM_X4(r0, r1, r2, r3, addr) \
    asm volatile("ldmatrix.sync.aligned.m8n8.x4.shared.b16 {%0,%1,%2,%3}, [%4];" \
                 : "=r"(r0), "=r"(r1), "=r"(r2), "=r"(r3) : "r"(addr))

#define MMA_BF16(d, a, b0, b1) \
    asm volatile("mma.sync.aligned.m16n8k16.row.col.f32.bf16.bf16.f32 " \
                 "{%0,%1,%2,%3},{%4,%5,%6,%7},{%8,%9},{%0,%1,%2,%3};" \
                 : "+f"((d)[0]), "+f"((d)[1]), "+f"((d)[2]), "+f"((d)[3]) \
                 : "r"((a)[0]), "r"((a)[1]), "r"((a)[2]), "r"((a)[3]), \
                   "r"(b0), "r"(b1))

__device__ __forceinline__ uint32_t bsplit_hi2(float x, float y, float& rx, float& ry) {
    __nv_bfloat162 h;
    h.x = __float2bfloat16(x);
    h.y = __float2bfloat16(y);
    rx = x - __bfloat162float(h.x);
    ry = y - __bfloat162float(h.y);
    return *reinterpret_cast<uint32_t*>(&h);
}
__device__ __forceinline__ uint32_t pack_bf2(float x, float y) {
    __nv_bfloat162 h;
    h.x = __float2bfloat16(x);
    h.y = __float2bfloat16(y);
    return *reinterpret_cast<uint32_t*>(&h);
}

// ---------------- graph build ----------------
__global__ void k_zero_graph(int n) {
    int i = blockIdx.x * blockDim.x + threadIdx.x;
    if (i < n) { g_cnt[i] = 0; g_cursor[i] = 0; }
    if (blockIdx.x == 0 && threadIdx.x < DH) {
        g_bnsum1[threadIdx.x] = 0.f; g_bnsq1[threadIdx.x] = 0.f;
        g_bnsum2[threadIdx.x] = 0.f; g_bnsq2[threadIdx.x] = 0.f;
    }
}

__global__ void k_hist(const int* __restrict__ ei, int e) {
    int i = blockIdx.x * blockDim.x + threadIdx.x;
    if (i < e) atomicAdd(&g_cnt[ei[e + i]], 1);
}

__global__ void k_dinv(int n) {
    int i = blockIdx.x * blockDim.x + threadIdx.x;
    if (i < n) g_dinv[i] = rsqrtf((float)(g_cnt[i] + 1));
}

__global__ void k_scan1(int n) {
    __shared__ int warpsum[32];
    int i = blockIdx.x * 1024 + threadIdx.x;
    int v = (i < n) ? g_cnt[i] : 0;
    int lane = threadIdx.x & 31, wid = threadIdx.x >> 5;
    int incl = v;
#pragma unroll
    for (int o = 1; o < 32; o <<= 1) {
        int t = __shfl_up_sync(0xffffffffu, incl, o);
        if (lane >= o) incl += t;
    }
    if (lane == 31) warpsum[wid] = incl;
    __syncthreads();
    if (wid == 0) {
        int s = warpsum[lane];
        int si = s;
#pragma unroll
        for (int o = 1; o < 32; o <<= 1) {
            int t = __shfl_up_sync(0xffffffffu, si, o);
            if (lane >= o) si += t;
        }
        warpsum[lane] = si - s;
    }
    __syncthreads();
    int excl = incl - v + warpsum[wid];
    if (i < n) g_rowoff[i] = excl;
    if (threadIdx.x == 1023) g_blocksum[blockIdx.x] = excl + v;
}

__global__ void k_scan2(int nb) {
    __shared__ int s[128];
    int t = threadIdx.x;
    int v = (t < nb) ? g_blocksum[t] : 0;
    s[t] = v;
    __syncthreads();
    for (int o = 1; o < 128; o <<= 1) {
        int x = (t >= o) ? s[t - o] : 0;
        __syncthreads();
        s[t] += x;
        __syncthreads();
    }
    if (t < nb) g_blockpref[t] = s[t] - v;
}

__global__ void k_scan3(int n) {
    int i = blockIdx.x * blockDim.x + threadIdx.x;
    if (i < n) g_rowoff[i] += g_blockpref[i >> 10];
}

__global__ void k_fill(const int* __restrict__ ei, int e) {
    int i = blockIdx.x * blockDim.x + threadIdx.x;
    if (i < e) {
        int s = ei[i];
        int d = ei[e + i];
        int pos = atomicAdd(&g_cursor[d], 1);
        g_col[g_rowoff[d] + pos] = s;
    }
}

// ======== HMMA GEMM (R9-proven): C(fp16) = dinv[row]*(relu(bn(A))@W) ========
// bf16 hi/lo split, 3 mma.sync passes, fp32 accum.
// FUSE: BN scale/shift computed in-kernel from sums (k_bnparams fused away).
#define LDS_H 40

template <int NCOLS, bool FUSE>
__global__ __launch_bounds__(256) void k_mma(const float* __restrict__ A,
                                             const float* __restrict__ W,
                                             __half* __restrict__ C,
                                             const float* __restrict__ sumArr,
                                             const float* __restrict__ sqArr,
                                             const float* __restrict__ gma,
                                             const float* __restrict__ bta,
                                             float inv_n, int n) {
    constexpr int NT = NCOLS / 16;
    constexpr int NSH = (NCOLS == 128) ? 7 : 6;
    __shared__ __align__(16) __nv_bfloat16 sAhi[128 * LDS_H];
    __shared__ __align__(16) __nv_bfloat16 sAlo[128 * LDS_H];
    __shared__ __align__(16) __nv_bfloat16 sWhi[NCOLS * LDS_H];
    __shared__ __align__(16) __nv_bfloat16 sWlo[NCOLS * LDS_H];
    __shared__ float s_scale[DH];
    __shared__ float s_shift[DH];

    int tid = threadIdx.x;
    int wid = tid >> 5, lane = tid & 31;
    int warp_m = wid & 3, warp_n = wid >> 2;
    int row0 = blockIdx.x * 128;
    int g = lane >> 2, t = lane & 3;

    if (FUSE && tid < DH) {
        float mean = sumArr[tid] * inv_n;
        float var = sqArr[tid] * inv_n - mean * mean;
        float s = gma[tid] * rsqrtf(var + EPS);
        s_scale[tid] = s;
        s_shift[tid] = bta[tid] - mean * s;
    }
    if (FUSE) __syncthreads();

    uint32_t uAhi = smem_u32(sAhi), uAlo = smem_u32(sAlo);
    uint32_t uWhi = smem_u32(sWhi), uWlo = smem_u32(sWlo);

    float acc[2][NT][4];
#pragma unroll
    for (int i = 0; i < 2; i++)
#pragma unroll
        for (int j = 0; j < NT; j++)
#pragma unroll
            for (int q = 0; q < 4; q++) acc[i][j][q] = 0.f;

    uint32_t a_off = ((warp_m * 32 + (lane & 15)) * LDS_H + (lane >> 4) * 8) * 2;
    uint32_t b_off = ((warp_n * (NCOLS / 2) + (lane & 7) + ((lane & 16) ? 8 : 0)) * LDS_H
                      + ((lane >> 3) & 1) * 8) * 2;

    for (int kc = 0; kc < 4; kc++) {
#pragma unroll
        for (int it = 0; it < 4; it++) {
            int idx = tid + it * 256;
            int r = idx >> 3;
            int c4 = idx & 7;
            int row = row0 + r;
            float4 v = make_float4(0.f, 0.f, 0.f, 0.f);
            if (row < n)
                v = reinterpret_cast<const float4*>(A)[(size_t)row * 32 + kc * 8 + c4];
            if (FUSE) {
                int k = kc * 32 + c4 * 4;
                v.x = fmaxf(0.f, v.x * s_scale[k + 0] + s_shift[k + 0]);
                v.y = fmaxf(0.f, v.y * s_scale[k + 1] + s_shift[k + 1]);
                v.z = fmaxf(0.f, v.z * s_scale[k + 2] + s_shift[k + 2]);
                v.w = fmaxf(0.f, v.w * s_scale[k + 3] + s_shift[k + 3]);
            }
            float rx, ry, rz, rw;
            uint2 hh, ll;
            hh.x = bsplit_hi2(v.x, v.y, rx, ry);
            hh.y = bsplit_hi2(v.z, v.w, rz, rw);
            ll.x = pack_bf2(rx, ry);
            ll.y = pack_bf2(rz, rw);
            int ho = r * LDS_H + c4 * 4;
            *reinterpret_cast<uint2*>(&sAhi[ho]) = hh;
            *reinterpret_cast<uint2*>(&sAlo[ho]) = ll;
        }
#pragma unroll
        for (int it = 0; it < (32 * NCOLS) / 256; it++) {
            int idx = tid + it * 256;
            int nn_ = idx & (NCOLS - 1);
            int kk_ = idx >> NSH;
            float w = W[(size_t)(kc * 32 + kk_) * NCOLS + nn_];
            __nv_bfloat16 wh = __float2bfloat16(w);
            __nv_bfloat16 wl = __float2bfloat16(w - __bfloat162float(wh));
            sWhi[nn_ * LDS_H + kk_] = wh;
            sWlo[nn_ * LDS_H + kk_] = wl;
        }
        __syncthreads();

#pragma unroll
        for (int ks = 0; ks < 2; ks++) {
            uint32_t k0b = ks * 16 * 2;
            uint32_t ah[2][4], al[2][4];
#pragma unroll
            for (int mt = 0; mt < 2; mt++) {
                uint32_t ao = a_off + k0b + mt * 16 * LDS_H * 2;
                LDSM_X4(ah[mt][0], ah[mt][1], ah[mt][2], ah[mt][3], uAhi + ao);
                LDSM_X4(al[mt][0], al[mt][1], al[mt][2], al[mt][3], uAlo + ao);
            }
#pragma unroll
            for (int nt2 = 0; nt2 < NT / 2; nt2++) {
                uint32_t bo = b_off + k0b + nt2 * 16 * LDS_H * 2;
                uint32_t bh[4], bl[4];
                LDSM_X4(bh[0], bh[1], bh[2], bh[3], uWhi + bo);
                LDSM_X4(bl[0], bl[1], bl[2], bl[3], uWlo + bo);
#pragma unroll
                for (int mt = 0; mt < 2; mt++) {
#pragma unroll
                    for (int sb = 0; sb < 2; sb++) {
                        float* d = acc[mt][nt2 * 2 + sb];
                        MMA_BF16(d, ah[mt], bh[2 * sb], bh[2 * sb + 1]);
                        MMA_BF16(d, ah[mt], bl[2 * sb], bl[2 * sb + 1]);
                        MMA_BF16(d, al[mt], bh[2 * sb], bh[2 * sb + 1]);
                    }
                }
            }
        }
        __syncthreads();
    }

    // ---- epilogue: pre-scale by dinv[row], fp16 out ----
#pragma unroll
    for (int mt = 0; mt < 2; mt++) {
        int r0 = row0 + warp_m * 32 + mt * 16 + g;
        float d0 = (r0 < n) ? g_dinv[r0] : 0.f;
        float d1 = (r0 + 8 < n) ? g_dinv[r0 + 8] : 0.f;
#pragma unroll
        for (int nt = 0; nt < NT; nt++) {
            int col = warp_n * (NCOLS / 2) + nt * 8 + 2 * t;
            if (r0 < n)
                *reinterpret_cast<__half2*>(&C[(size_t)r0 * NCOLS + col]) =
                    __floats2half2_rn(acc[mt][nt][0] * d0, acc[mt][nt][1] * d0);
            if (r0 + 8 < n)
                *reinterpret_cast<__half2*>(&C[(size_t)(r0 + 8) * NCOLS + col]) =
                    __floats2half2_rn(acc[mt][nt][2] * d1, acc[mt][nt][3] * d1);
        }
    }
}

// ---------------- aggregation over pre-scaled fp16 messages ----------------
template <int LANES, bool STATS, bool SOFTMAX>
__global__ __launch_bounds__(256) void k_agg(const uint2* __restrict__ t,
                                             float* __restrict__ outp,
                                             const float* __restrict__ bias,
                                             float* __restrict__ sumArr,
                                             float* __restrict__ sqArr, int n) {
    constexpr int SUBS = 256 / LANES;
    int sub = threadIdx.x / LANES;
    int lane = threadIdx.x % LANES;
    unsigned mask = (LANES == 32) ? 0xffffffffu : (0xffffu << (threadIdx.x & 16));
    int stride = gridDim.x * SUBS;

    float4 lsum = make_float4(0, 0, 0, 0);
    float4 lsq = make_float4(0, 0, 0, 0);
    float4 b4 = reinterpret_cast<const float4*>(bias)[lane];

    for (int node = blockIdx.x * SUBS + sub; node < n; node += stride) {
        float dn = g_dinv[node];
        uint2 u0 = t[(size_t)node * LANES + lane];
        float2 s01 = __half22float2(*reinterpret_cast<__half2*>(&u0.x));
        float2 s23 = __half22float2(*reinterpret_cast<__half2*>(&u0.y));
        float4 acc = make_float4(s01.x, s01.y, s23.x, s23.y);   // self message
        float4 acc2 = make_float4(0.f, 0.f, 0.f, 0.f);
        int start = g_rowoff[node];
        int cnt = g_cnt[node];
        int base = 0;
        for (; base + LANES <= cnt; base += LANES) {
            int s = g_col[start + base + lane];
#pragma unroll 16
            for (int k = 0; k < LANES; k++) {
                int ss = __shfl_sync(mask, s, k, LANES);
                uint2 u = t[(size_t)ss * LANES + lane];
                float2 f01 = __half22float2(*reinterpret_cast<__half2*>(&u.x));
                float2 f23 = __half22float2(*reinterpret_cast<__half2*>(&u.y));
                if (k & 1) {
                    acc2.x += f01.x; acc2.y += f01.y; acc2.z += f23.x; acc2.w += f23.y;
                } else {
                    acc.x += f01.x; acc.y += f01.y; acc.z += f23.x; acc.w += f23.y;
                }
            }
        }
        int rem = cnt - base;
        if (rem > 0) {
            int s = (lane < rem) ? g_col[start + base + lane] : 0;
            for (int k = 0; k < rem; k++) {
                int ss = __shfl_sync(mask, s, k, LANES);
                uint2 u = t[(size_t)ss * LANES + lane];
                float2 f01 = __half22float2(*reinterpret_cast<__half2*>(&u.x));
                float2 f23 = __half22float2(*reinterpret_cast<__half2*>(&u.y));
                if (k & 1) {
                    acc2.x += f01.x; acc2.y += f01.y; acc2.z += f23.x; acc2.w += f23.y;
                } else {
                    acc.x += f01.x; acc.y += f01.y; acc.z += f23.x; acc.w += f23.y;
                }
            }
        }
        acc.x += acc2.x; acc.y += acc2.y; acc.z += acc2.z; acc.w += acc2.w;
        acc.x = acc.x * dn + b4.x;
        acc.y = acc.y * dn + b4.y;
        acc.z = acc.z * dn + b4.z;
        acc.w = acc.w * dn + b4.w;

        if (SOFTMAX) {
            float m = fmaxf(fmaxf(acc.x, acc.y), fmaxf(acc.z, acc.w));
#pragma unroll
            for (int o = LANES / 2; o >= 1; o >>= 1)
                m = fmaxf(m, __shfl_xor_sync(mask, m, o, LANES));
            float4 e;
            e.x = __expf(acc.x - m); e.y = __expf(acc.y - m);
            e.z = __expf(acc.z - m); e.w = __expf(acc.w - m);
            float ssum = e.x + e.y + e.z + e.w;
#pragma unroll
            for (int o = LANES / 2; o >= 1; o >>= 1)
                ssum += __shfl_xor_sync(mask, ssum, o, LANES);
            float inv = 1.f / ssum;
            e.x *= inv; e.y *= inv; e.z *= inv; e.w *= inv;
            reinterpret_cast<float4*>(outp)[(size_t)node * LANES + lane] = e;
        } else {
            reinterpret_cast<float4*>(outp)[(size_t)node * LANES + lane] = acc;
            if (STATS) {
                lsum.x += acc.x; lsum.y += acc.y; lsum.z += acc.z; lsum.w += acc.w;
                lsq.x += acc.x * acc.x; lsq.y += acc.y * acc.y;
                lsq.z += acc.z * acc.z; lsq.w += acc.w * acc.w;
            }
        }
    }

    if constexpr (STATS) {
        __shared__ float4 ssumS[SUBS][32];
        __shared__ float4 ssqS[SUBS][32];
        ssumS[sub][lane] = lsum;
        ssqS[sub][lane] = lsq;
        __syncthreads();
        if (threadIdx.x < 32) {
            float4 a = make_float4(0, 0, 0, 0), b = make_float4(0, 0, 0, 0);
#pragma unroll
            for (int w2 = 0; w2 < SUBS; w2++) {
                float4 u = ssumS[w2][threadIdx.x], q = ssqS[w2][threadIdx.x];
                a.x += u.x; a.y += u.y; a.z += u.z; a.w += u.w;
                b.x += q.x; b.y += q.y; b.z += q.z; b.w += q.w;
            }
            int c = threadIdx.x * 4;
            atomicAdd(&sumArr[c + 0], a.x); atomicAdd(&sumArr[c + 1], a.y);
            atomicAdd(&sumArr[c + 2], a.z); atomicAdd(&sumArr[c + 3], a.w);
            atomicAdd(&sqArr[c + 0], b.x);  atomicAdd(&sqArr[c + 1], b.y);
            atomicAdd(&sqArr[c + 2], b.z);  atomicAdd(&sqArr[c + 3], b.w);
        }
    }
}

// ---------------- host ----------------
extern "C" void kernel_launch(void* const* d_in, const int* in_sizes, int n_in,
                              void* d_out, int out_size) {
    const float* x  = (const float*)d_in[0];
    const int*   ei = (const int*)d_in[1];
    const float* W1 = (const float*)d_in[2];
    const float* b1 = (const float*)d_in[3];
    const float* W2 = (const float*)d_in[4];
    const float* b2 = (const float*)d_in[5];
    const float* W3 = (const float*)d_in[6];
    const float* b3 = (const float*)d_in[7];
    const float* g1 = (const float*)d_in[8];
    const float* be1 = (const float*)d_in[9];
    const float* g2 = (const float*)d_in[10];
    const float* be2 = (const float*)d_in[11];

    int n = in_sizes[0] / 128;
    int e = in_sizes[1] / 2;

    static __half* msg = nullptr;
    static float* buf = nullptr;
    static float *sum1, *sq1, *sum2, *sq2;
    static cudaStream_t s2 = nullptr;
    static cudaEvent_t ev1 = nullptr, ev2 = nullptr;
    if (!msg) {
        cudaGetSymbolAddress((void**)&msg, g_msg);
        cudaGetSymbolAddress((void**)&buf, g_buf);
        cudaGetSymbolAddress((void**)&sum1, g_bnsum1);
        cudaGetSymbolAddress((void**)&sq1, g_bnsq1);
        cudaGetSymbolAddress((void**)&sum2, g_bnsum2);
        cudaGetSymbolAddress((void**)&sq2, g_bnsq2);
        cudaStreamCreateWithFlags(&s2, cudaStreamNonBlocking);
        cudaEventCreateWithFlags(&ev1, cudaEventDisableTiming);
        cudaEventCreateWithFlags(&ev2, cudaEventDisableTiming);
    }
    const uint2* msg2 = (const uint2*)msg;

    int nb_scan = (n + 1023) / 1024;
    int gb = (n + 127) / 128;
    int eb = (e + 255) / 256;
    int nb256 = (n + 255) / 256;
    float inv_n = 1.0f / (float)n;

    // ---- graph build on main stream; mma1 overlapped on s2 (dinv-only dep) ----
    k_zero_graph<<<nb256, 256>>>(n);
    k_hist<<<eb, 256>>>(ei, e);
    k_dinv<<<nb256, 256>>>(n);
    cudaEventRecord(ev1, 0);
    cudaStreamWaitEvent(s2, ev1, 0);
    k_mma<128, false><<<gb, 256, 0, s2>>>(x, W1, msg, nullptr, nullptr, nullptr,
                                          nullptr, inv_n, n);
    cudaEventRecord(ev2, s2);
    k_scan1<<<nb_scan, 1024>>>(n);
    k_scan2<<<1, 128>>>(nb_scan);
    k_scan3<<<nb256, 256>>>(n);
    k_fill<<<eb, 256>>>(ei, e);
    cudaStreamWaitEvent(0, ev2, 0);

    // layer 1  (BN params for layer-2 GEMM computed inside k_mma<.,true>)
    k_agg<32, true, false><<<1024, 256>>>(msg2, buf, b1, sum1, sq1, n);

    // layer 2
    k_mma<128, true><<<gb, 256>>>(buf, W2, msg, sum1, sq1, g1, be1, inv_n, n);
    k_agg<32, true, false><<<1024, 256>>>(msg2, buf, b2, sum2, sq2, n);

    // layer 3 + softmax
    k_mma<64, true><<<gb, 256>>>(buf, W3, msg, sum2, sq2, g2, be2, inv_n, n);
    k_agg<16, false, true><<<1024, 256>>>(msg2, (float*)d_out, b3, nullptr, nullptr, n);
}

// round 14
// speedup vs baseline: 1.0810x; 1.0476x over previous
#include <cuda_runtime.h>
#include <cuda_fp16.h>
#include <cuda_bf16.h>
#include <cstdint>

#define NN 100000
#define EE 3200000
#define DH 128
#define EPS 1e-5f

// ---------------- device scratch (static, no allocation) ----------------
__device__ int    g_cnt[NN];
__device__ int    g_cursor[NN];
__device__ int    g_rowoff[NN];
__device__ float  g_dinv[NN];
__device__ int    g_col[EE];
__device__ int    g_blocksum[128];
__device__ int    g_blockpref[128];
__device__ float  g_bnsum1[DH];
__device__ float  g_bnsq1[DH];
__device__ float  g_bnsum2[DH];
__device__ float  g_bnsq2[DH];
__device__ float  g_bnscale[DH];
__device__ float  g_bnshift[DH];
__device__ __half g_msg[NN * DH];      // GEMM out * dinv (fp16)
__device__ float  g_buf[NN * DH];      // agg out (fp32)

__device__ __forceinline__ uint32_t smem_u32(const void* p) {
    uint32_t a;
    asm("{ .reg .u64 tmp; cvta.to.shared.u64 tmp, %1; cvt.u32.u64 %0, tmp; }"
        : "=r"(a) : "l"(p));
    return a;
}

#define LDSM_X4(r0, r1, r2, r3, addr) \
    asm volatile("ldmatrix.sync.aligned.m8n8.x4.shared.b16 {%0,%1,%2,%3}, [%4];" \
                 : "=r"(r0), "=r"(r1), "=r"(r2), "=r"(r3) : "r"(addr))

#define MMA_BF16(d, a, b0, b1) \
    asm volatile("mma.sync.aligned.m16n8k16.row.col.f32.bf16.bf16.f32 " \
                 "{%0,%1,%2,%3},{%4,%5,%6,%7},{%8,%9},{%0,%1,%2,%3};" \
                 : "+f"((d)[0]), "+f"((d)[1]), "+f"((d)[2]), "+f"((d)[3]) \
                 : "r"((a)[0]), "r"((a)[1]), "r"((a)[2]), "r"((a)[3]), \
                   "r"(b0), "r"(b1))

__device__ __forceinline__ uint32_t bsplit_hi2(float x, float y, float& rx, float& ry) {
    __nv_bfloat162 h;
    h.x = __float2bfloat16(x);
    h.y = __float2bfloat16(y);
    rx = x - __bfloat162float(h.x);
    ry = y - __bfloat162float(h.y);
    return *reinterpret_cast<uint32_t*>(&h);
}
__device__ __forceinline__ uint32_t pack_bf2(float x, float y) {
    __nv_bfloat162 h;
    h.x = __float2bfloat16(x);
    h.y = __float2bfloat16(y);
    return *reinterpret_cast<uint32_t*>(&h);
}

// ---------------- graph build ----------------
__global__ void k_zero_graph(int n) {
    int i = blockIdx.x * blockDim.x + threadIdx.x;
    if (i < n) { g_cnt[i] = 0; g_cursor[i] = 0; }
    if (blockIdx.x == 0 && threadIdx.x < DH) {
        g_bnsum1[threadIdx.x] = 0.f; g_bnsq1[threadIdx.x] = 0.f;
        g_bnsum2[threadIdx.x] = 0.f; g_bnsq2[threadIdx.x] = 0.f;
    }
}

__global__ void k_hist(const int* __restrict__ ei, int e) {
    int i = blockIdx.x * blockDim.x + threadIdx.x;
    if (i < e) atomicAdd(&g_cnt[ei[e + i]], 1);
}

// scan of counts; also writes dinv (fused k_dinv)
__global__ void k_scan1(int n) {
    __shared__ int warpsum[32];
    int i = blockIdx.x * 1024 + threadIdx.x;
    int v = (i < n) ? g_cnt[i] : 0;
    if (i < n) g_dinv[i] = rsqrtf((float)(v + 1));
    int lane = threadIdx.x & 31, wid = threadIdx.x >> 5;
    int incl = v;
#pragma unroll
    for (int o = 1; o < 32; o <<= 1) {
        int t = __shfl_up_sync(0xffffffffu, incl, o);
        if (lane >= o) incl += t;
    }
    if (lane == 31) warpsum[wid] = incl;
    __syncthreads();
    if (wid == 0) {
        int s = warpsum[lane];
        int si = s;
#pragma unroll
        for (int o = 1; o < 32; o <<= 1) {
            int t = __shfl_up_sync(0xffffffffu, si, o);
            if (lane >= o) si += t;
        }
        warpsum[lane] = si - s;
    }
    __syncthreads();
    int excl = incl - v + warpsum[wid];
    if (i < n) g_rowoff[i] = excl;
    if (threadIdx.x == 1023) g_blocksum[blockIdx.x] = excl + v;
}

__global__ void k_scan2(int nb) {
    __shared__ int s[128];
    int t = threadIdx.x;
    int v = (t < nb) ? g_blocksum[t] : 0;
    s[t] = v;
    __syncthreads();
    for (int o = 1; o < 128; o <<= 1) {
        int x = (t >= o) ? s[t - o] : 0;
        __syncthreads();
        s[t] += x;
        __syncthreads();
    }
    if (t < nb) g_blockpref[t] = s[t] - v;
}

__global__ void k_scan3(int n) {
    int i = blockIdx.x * blockDim.x + threadIdx.x;
    if (i < n) g_rowoff[i] += g_blockpref[i >> 10];
}

__global__ void k_fill(const int* __restrict__ ei, int e) {
    int i = blockIdx.x * blockDim.x + threadIdx.x;
    if (i < e) {
        int s = ei[i];
        int d = ei[e + i];
        int pos = atomicAdd(&g_cursor[d], 1);
        g_col[g_rowoff[d] + pos] = s;
    }
}

// ======== HMMA GEMM (R9-proven): C(fp16) = dinv[row]*(act(A)@W) ========
// bf16 hi/lo split, 3 mma.sync passes, fp32 accum.
// Epilogue computes dinv from g_cnt directly (no k_dinv dependency).
#define LDS_H 40

template <int NCOLS, bool FUSE>
__global__ __launch_bounds__(256) void k_mma(const float* __restrict__ A,
                                             const float* __restrict__ W,
                                             __half* __restrict__ C, int n) {
    constexpr int NT = NCOLS / 16;
    constexpr int NSH = (NCOLS == 128) ? 7 : 6;
    __shared__ __align__(16) __nv_bfloat16 sAhi[128 * LDS_H];
    __shared__ __align__(16) __nv_bfloat16 sAlo[128 * LDS_H];
    __shared__ __align__(16) __nv_bfloat16 sWhi[NCOLS * LDS_H];
    __shared__ __align__(16) __nv_bfloat16 sWlo[NCOLS * LDS_H];

    int tid = threadIdx.x;
    int wid = tid >> 5, lane = tid & 31;
    int warp_m = wid & 3, warp_n = wid >> 2;
    int row0 = blockIdx.x * 128;
    int g = lane >> 2, t = lane & 3;

    uint32_t uAhi = smem_u32(sAhi), uAlo = smem_u32(sAlo);
    uint32_t uWhi = smem_u32(sWhi), uWlo = smem_u32(sWlo);

    float acc[2][NT][4];
#pragma unroll
    for (int i = 0; i < 2; i++)
#pragma unroll
        for (int j = 0; j < NT; j++)
#pragma unroll
            for (int q = 0; q < 4; q++) acc[i][j][q] = 0.f;

    uint32_t a_off = ((warp_m * 32 + (lane & 15)) * LDS_H + (lane >> 4) * 8) * 2;
    uint32_t b_off = ((warp_n * (NCOLS / 2) + (lane & 7) + ((lane & 16) ? 8 : 0)) * LDS_H
                      + ((lane >> 3) & 1) * 8) * 2;

    for (int kc = 0; kc < 4; kc++) {
#pragma unroll
        for (int it = 0; it < 4; it++) {
            int idx = tid + it * 256;
            int r = idx >> 3;
            int c4 = idx & 7;
            int row = row0 + r;
            float4 v = make_float4(0.f, 0.f, 0.f, 0.f);
            if (row < n)
                v = reinterpret_cast<const float4*>(A)[(size_t)row * 32 + kc * 8 + c4];
            if (FUSE) {
                int k = kc * 32 + c4 * 4;
                v.x = fmaxf(0.f, v.x * g_bnscale[k + 0] + g_bnshift[k + 0]);
                v.y = fmaxf(0.f, v.y * g_bnscale[k + 1] + g_bnshift[k + 1]);
                v.z = fmaxf(0.f, v.z * g_bnscale[k + 2] + g_bnshift[k + 2]);
                v.w = fmaxf(0.f, v.w * g_bnscale[k + 3] + g_bnshift[k + 3]);
            }
            float rx, ry, rz, rw;
            uint2 hh, ll;
            hh.x = bsplit_hi2(v.x, v.y, rx, ry);
            hh.y = bsplit_hi2(v.z, v.w, rz, rw);
            ll.x = pack_bf2(rx, ry);
            ll.y = pack_bf2(rz, rw);
            int ho = r * LDS_H + c4 * 4;
            *reinterpret_cast<uint2*>(&sAhi[ho]) = hh;
            *reinterpret_cast<uint2*>(&sAlo[ho]) = ll;
        }
#pragma unroll
        for (int it = 0; it < (32 * NCOLS) / 256; it++) {
            int idx = tid + it * 256;
            int nn_ = idx & (NCOLS - 1);
            int kk_ = idx >> NSH;
            float w = W[(size_t)(kc * 32 + kk_) * NCOLS + nn_];
            __nv_bfloat16 wh = __float2bfloat16(w);
            __nv_bfloat16 wl = __float2bfloat16(w - __bfloat162float(wh));
            sWhi[nn_ * LDS_H + kk_] = wh;
            sWlo[nn_ * LDS_H + kk_] = wl;
        }
        __syncthreads();

#pragma unroll
        for (int ks = 0; ks < 2; ks++) {
            uint32_t k0b = ks * 16 * 2;
            uint32_t ah[2][4], al[2][4];
#pragma unroll
            for (int mt = 0; mt < 2; mt++) {
                uint32_t ao = a_off + k0b + mt * 16 * LDS_H * 2;
                LDSM_X4(ah[mt][0], ah[mt][1], ah[mt][2], ah[mt][3], uAhi + ao);
                LDSM_X4(al[mt][0], al[mt][1], al[mt][2], al[mt][3], uAlo + ao);
            }
#pragma unroll
            for (int nt2 = 0; nt2 < NT / 2; nt2++) {
                uint32_t bo = b_off + k0b + nt2 * 16 * LDS_H * 2;
                uint32_t bh[4], bl[4];
                LDSM_X4(bh[0], bh[1], bh[2], bh[3], uWhi + bo);
                LDSM_X4(bl[0], bl[1], bl[2], bl[3], uWlo + bo);
#pragma unroll
                for (int mt = 0; mt < 2; mt++) {
#pragma unroll
                    for (int sb = 0; sb < 2; sb++) {
                        float* d = acc[mt][nt2 * 2 + sb];
                        MMA_BF16(d, ah[mt], bh[2 * sb], bh[2 * sb + 1]);
                        MMA_BF16(d, ah[mt], bl[2 * sb], bl[2 * sb + 1]);
                        MMA_BF16(d, al[mt], bh[2 * sb], bh[2 * sb + 1]);
                    }
                }
            }
        }
        __syncthreads();
    }

    // ---- epilogue: dinv computed from cnt (no k_dinv dependency) ----
#pragma unroll
    for (int mt = 0; mt < 2; mt++) {
        int r0 = row0 + warp_m * 32 + mt * 16 + g;
        float d0 = (r0 < n) ? rsqrtf((float)(g_cnt[r0] + 1)) : 0.f;
        float d1 = (r0 + 8 < n) ? rsqrtf((float)(g_cnt[r0 + 8] + 1)) : 0.f;
#pragma unroll
        for (int nt = 0; nt < NT; nt++) {
            int col = warp_n * (NCOLS / 2) + nt * 8 + 2 * t;
            if (r0 < n)
                *reinterpret_cast<__half2*>(&C[(size_t)r0 * NCOLS + col]) =
                    __floats2half2_rn(acc[mt][nt][0] * d0, acc[mt][nt][1] * d0);
            if (r0 + 8 < n)
                *reinterpret_cast<__half2*>(&C[(size_t)(r0 + 8) * NCOLS + col]) =
                    __floats2half2_rn(acc[mt][nt][2] * d1, acc[mt][nt][3] * d1);
        }
    }
}

// ---------------- BN param kernel ----------------
__global__ void k_bnparams(const float* __restrict__ g, const float* __restrict__ be,
                           const float* __restrict__ sumArr, const float* __restrict__ sqArr,
                           float inv_n) {
    int c = threadIdx.x;
    if (c < DH) {
        float mean = sumArr[c] * inv_n;
        float var = sqArr[c] * inv_n - mean * mean;
        float s = g[c] * rsqrtf(var + EPS);
        g_bnscale[c] = s;
        g_bnshift[c] = be[c] - mean * s;
    }
}

// ---------------- aggregation over pre-scaled fp16 messages ----------------
template <int LANES, bool STATS, bool SOFTMAX>
__global__ __launch_bounds__(256) void k_agg(const uint2* __restrict__ t,
                                             float* __restrict__ outp,
                                             const float* __restrict__ bias,
                                             float* __restrict__ sumArr,
                                             float* __restrict__ sqArr, int n) {
    constexpr int SUBS = 256 / LANES;
    int sub = threadIdx.x / LANES;
    int lane = threadIdx.x % LANES;
    unsigned mask = (LANES == 32) ? 0xffffffffu : (0xffffu << (threadIdx.x & 16));
    int stride = gridDim.x * SUBS;

    float4 lsum = make_float4(0, 0, 0, 0);
    float4 lsq = make_float4(0, 0, 0, 0);
    float4 b4 = reinterpret_cast<const float4*>(bias)[lane];

    for (int node = blockIdx.x * SUBS + sub; node < n; node += stride) {
        float dn = g_dinv[node];
        uint2 u0 = t[(size_t)node * LANES + lane];
        float2 s01 = __half22float2(*reinterpret_cast<__half2*>(&u0.x));
        float2 s23 = __half22float2(*reinterpret_cast<__half2*>(&u0.y));
        float4 acc = make_float4(s01.x, s01.y, s23.x, s23.y);   // self message
        float4 acc2 = make_float4(0.f, 0.f, 0.f, 0.f);
        int start = g_rowoff[node];
        int cnt = g_cnt[node];
        int base = 0;
        for (; base + LANES <= cnt; base += LANES) {
            int s = g_col[start + base + lane];
#pragma unroll 16
            for (int k = 0; k < LANES; k++) {
                int ss = __shfl_sync(mask, s, k, LANES);
                uint2 u = t[(size_t)ss * LANES + lane];
                float2 f01 = __half22float2(*reinterpret_cast<__half2*>(&u.x));
                float2 f23 = __half22float2(*reinterpret_cast<__half2*>(&u.y));
                if (k & 1) {
                    acc2.x += f01.x; acc2.y += f01.y; acc2.z += f23.x; acc2.w += f23.y;
                } else {
                    acc.x += f01.x; acc.y += f01.y; acc.z += f23.x; acc.w += f23.y;
                }
            }
        }
        int rem = cnt - base;
        if (rem > 0) {
            int s = (lane < rem) ? g_col[start + base + lane] : 0;
            for (int k = 0; k < rem; k++) {
                int ss = __shfl_sync(mask, s, k, LANES);
                uint2 u = t[(size_t)ss * LANES + lane];
                float2 f01 = __half22float2(*reinterpret_cast<__half2*>(&u.x));
                float2 f23 = __half22float2(*reinterpret_cast<__half2*>(&u.y));
                if (k & 1) {
                    acc2.x += f01.x; acc2.y += f01.y; acc2.z += f23.x; acc2.w += f23.y;
                } else {
                    acc.x += f01.x; acc.y += f01.y; acc.z += f23.x; acc.w += f23.y;
                }
            }
        }
        acc.x += acc2.x; acc.y += acc2.y; acc.z += acc2.z; acc.w += acc2.w;
        acc.x = acc.x * dn + b4.x;
        acc.y = acc.y * dn + b4.y;
        acc.z = acc.z * dn + b4.z;
        acc.w = acc.w * dn + b4.w;

        if (SOFTMAX) {
            float m = fmaxf(fmaxf(acc.x, acc.y), fmaxf(acc.z, acc.w));
#pragma unroll
            for (int o = LANES / 2; o >= 1; o >>= 1)
                m = fmaxf(m, __shfl_xor_sync(mask, m, o, LANES));
            float4 e;
            e.x = __expf(acc.x - m); e.y = __expf(acc.y - m);
            e.z = __expf(acc.z - m); e.w = __expf(acc.w - m);
            float ssum = e.x + e.y + e.z + e.w;
#pragma unroll
            for (int o = LANES / 2; o >= 1; o >>= 1)
                ssum += __shfl_xor_sync(mask, ssum, o, LANES);
            float inv = 1.f / ssum;
            e.x *= inv; e.y *= inv; e.z *= inv; e.w *= inv;
            reinterpret_cast<float4*>(outp)[(size_t)node * LANES + lane] = e;
        } else {
            reinterpret_cast<float4*>(outp)[(size_t)node * LANES + lane] = acc;
            if (STATS) {
                lsum.x += acc.x; lsum.y += acc.y; lsum.z += acc.z; lsum.w += acc.w;
                lsq.x += acc.x * acc.x; lsq.y += acc.y * acc.y;
                lsq.z += acc.z * acc.z; lsq.w += acc.w * acc.w;
            }
        }
    }

    if constexpr (STATS) {
        __shared__ float4 ssumS[SUBS][32];
        __shared__ float4 ssqS[SUBS][32];
        ssumS[sub][lane] = lsum;
        ssqS[sub][lane] = lsq;
        __syncthreads();
        if (threadIdx.x < 32) {
            float4 a = make_float4(0, 0, 0, 0), b = make_float4(0, 0, 0, 0);
#pragma unroll
            for (int w2 = 0; w2 < SUBS; w2++) {
                float4 u = ssumS[w2][threadIdx.x], q = ssqS[w2][threadIdx.x];
                a.x += u.x; a.y += u.y; a.z += u.z; a.w += u.w;
                b.x += q.x; b.y += q.y; b.z += q.z; b.w += q.w;
            }
            int c = threadIdx.x * 4;
            atomicAdd(&sumArr[c + 0], a.x); atomicAdd(&sumArr[c + 1], a.y);
            atomicAdd(&sumArr[c + 2], a.z); atomicAdd(&sumArr[c + 3], a.w);
            atomicAdd(&sqArr[c + 0], b.x);  atomicAdd(&sqArr[c + 1], b.y);
            atomicAdd(&sqArr[c + 2], b.z);  atomicAdd(&sqArr[c + 3], b.w);
        }
    }
}

// ---------------- host ----------------
extern "C" void kernel_launch(void* const* d_in, const int* in_sizes, int n_in,
                              void* d_out, int out_size) {
    const float* x  = (const float*)d_in[0];
    const int*   ei = (const int*)d_in[1];
    const float* W1 = (const float*)d_in[2];
    const float* b1 = (const float*)d_in[3];
    const float* W2 = (const float*)d_in[4];
    const float* b2 = (const float*)d_in[5];
    const float* W3 = (const float*)d_in[6];
    const float* b3 = (const float*)d_in[7];
    const float* g1 = (const float*)d_in[8];
    const float* be1 = (const float*)d_in[9];
    const float* g2 = (const float*)d_in[10];
    const float* be2 = (const float*)d_in[11];

    int n = in_sizes[0] / 128;
    int e = in_sizes[1] / 2;

    static __half* msg = nullptr;
    static float* buf = nullptr;
    static float *sum1, *sq1, *sum2, *sq2;
    static cudaStream_t s2 = nullptr;
    static cudaEvent_t ev1 = nullptr, ev2 = nullptr;
    if (!msg) {
        cudaGetSymbolAddress((void**)&msg, g_msg);
        cudaGetSymbolAddress((void**)&buf, g_buf);
        cudaGetSymbolAddress((void**)&sum1, g_bnsum1);
        cudaGetSymbolAddress((void**)&sq1, g_bnsq1);
        cudaGetSymbolAddress((void**)&sum2, g_bnsum2);
        cudaGetSymbolAddress((void**)&sq2, g_bnsq2);
        cudaStreamCreateWithFlags(&s2, cudaStreamNonBlocking);
        cudaEventCreateWithFlags(&ev1, cudaEventDisableTiming);
        cudaEventCreateWithFlags(&ev2, cudaEventDisableTiming);
    }
    const uint2* msg2 = (const uint2*)msg;

    int nb_scan = (n + 1023) / 1024;
    int gb = (n + 127) / 128;
    int eb = (e + 255) / 256;
    int nb256 = (n + 255) / 256;
    float inv_n = 1.0f / (float)n;

    // ---- graph build on main stream; mma1 on s2 depends only on hist ----
    k_zero_graph<<<nb256, 256>>>(n);
    k_hist<<<eb, 256>>>(ei, e);
    cudaEventRecord(ev1, 0);
    cudaStreamWaitEvent(s2, ev1, 0);
    k_mma<128, false><<<gb, 256, 0, s2>>>(x, W1, msg, n);
    cudaEventRecord(ev2, s2);
    k_scan1<<<nb_scan, 1024>>>(n);       // also writes g_dinv
    k_scan2<<<1, 128>>>(nb_scan);
    k_scan3<<<nb256, 256>>>(n);
    k_fill<<<eb, 256>>>(ei, e);
    cudaStreamWaitEvent(0, ev2, 0);

    // layer 1
    k_agg<32, true, false><<<1024, 256>>>(msg2, buf, b1, sum1, sq1, n);
    k_bnparams<<<1, 128>>>(g1, be1, sum1, sq1, inv_n);

    // layer 2
    k_mma<128, true><<<gb, 256>>>(buf, W2, msg, n);
    k_agg<32, true, false><<<1024, 256>>>(msg2, buf, b2, sum2, sq2, n);
    k_bnparams<<<1, 128>>>(g2, be2, sum2, sq2, inv_n);

    // layer 3 + softmax
    k_mma<64, true><<<gb, 256>>>(buf, W3, msg, n);
    k_agg<16, false, true><<<1024, 256>>>(msg2, (float*)d_out, b3, nullptr, nullptr, n);
}